// round 1
// baseline (speedup 1.0000x reference)
#include <cuda_runtime.h>
#include <math.h>

// Problem constants
#define BN 4
#define MM 8
#define NPTS 4096
#define HH 256
#define FDIM 512
#define SS 128
#define NSEG (BN*SS + 1)        // 513 (+1 dump segment)
#define NROWS_PP (BN*NPTS)      // 16384
#define NROWS_V  (BN*MM*NPTS)   // 131072

// Scratch (device globals: no allocation allowed)
__device__ float g_pp[NROWS_PP * HH];       // relu(LN(pf @ p_W))
__device__ float g_attn[NROWS_V];           // sigmoid attention, [(b*M+m)*Np + p]
__device__ float g_cnt[NSEG];
__device__ float g_asum[NSEG * MM];
__device__ float g_fsum[NSEG * HH];
__device__ float g_weighted[NROWS_PP * HH]; // softmax-weighted view features
__device__ float g_wvp[NROWS_PP * HH];      // relu(LN(weighted @ v_W))

__device__ __forceinline__ float warp_red(float v) {
    #pragma unroll
    for (int o = 16; o; o >>= 1) v += __shfl_xor_sync(0xffffffffu, v, o);
    return v;
}

// ---------------------------------------------------------------------------
// Generic fused GEMM + bias + LayerNorm(+ReLU).
// 32 rows per block, 256 threads. Warp w owns rows w*4..w*4+3.
// Lane owns cols lane + 32*c (c < N/32)  -> LN reductions are warp shuffles.
// Supports concatenated input: k < K1 from X1 (row len K1), else X2 (row len K-K1).
// ---------------------------------------------------------------------------
template<int N, int KTILE, bool RELU>
__global__ void gemm_ln_kernel(const float* __restrict__ X1, const float* __restrict__ X2,
                               int K1, int K,
                               const float* __restrict__ W, const float* __restrict__ bias,
                               const float* __restrict__ gamma, const float* __restrict__ beta,
                               float* __restrict__ Y)
{
    constexpr int CP = N / 32;
    extern __shared__ float sm[];
    float* Xs = sm;                // 32 * KTILE
    float* Ws = sm + 32 * KTILE;   // KTILE * N

    const int tid = threadIdx.x;
    const int wr = tid >> 5, lane = tid & 31;
    const int row0 = blockIdx.x * 32;

    float acc[4][CP];
    #pragma unroll
    for (int r = 0; r < 4; r++)
        #pragma unroll
        for (int c = 0; c < CP; c++) acc[r][c] = 0.f;

    for (int k0 = 0; k0 < K; k0 += KTILE) {
        for (int i = tid; i < 32 * KTILE; i += 256) {
            int r = i / KTILE, c = i % KTILE;
            int k = k0 + c;
            float v;
            if (k < K1) v = X1[(size_t)(row0 + r) * K1 + k];
            else        v = X2[(size_t)(row0 + r) * (K - K1) + (k - K1)];
            Xs[i] = v;
        }
        for (int i = tid; i < KTILE * N; i += 256) {
            int kk = i / N, n = i % N;
            Ws[i] = W[(size_t)(k0 + kk) * N + n];
        }
        __syncthreads();
        #pragma unroll
        for (int kk = 0; kk < KTILE; kk++) {
            float xv[4];
            #pragma unroll
            for (int r = 0; r < 4; r++) xv[r] = Xs[(wr * 4 + r) * KTILE + kk];
            #pragma unroll
            for (int c = 0; c < CP; c++) {
                float wv = Ws[kk * N + lane + 32 * c];
                #pragma unroll
                for (int r = 0; r < 4; r++) acc[r][c] = fmaf(xv[r], wv, acc[r][c]);
            }
        }
        __syncthreads();
    }

    // bias + LayerNorm (+ReLU)
    float gv[CP], bv[CP];
    #pragma unroll
    for (int c = 0; c < CP; c++) {
        int col = lane + 32 * c;
        float bb = bias[col];
        #pragma unroll
        for (int r = 0; r < 4; r++) acc[r][c] += bb;
        gv[c] = gamma[col];
        bv[c] = beta[col];
    }
    #pragma unroll
    for (int r = 0; r < 4; r++) {
        float s = 0.f;
        #pragma unroll
        for (int c = 0; c < CP; c++) s += acc[r][c];
        float mean = warp_red(s) * (1.f / N);
        float s2 = 0.f;
        #pragma unroll
        for (int c = 0; c < CP; c++) { float d = acc[r][c] - mean; s2 += d * d; }
        float inv = rsqrtf(warp_red(s2) * (1.f / N) + 1e-5f);
        size_t orow = (size_t)(row0 + wr * 4 + r) * N;
        #pragma unroll
        for (int c = 0; c < CP; c++) {
            float y = (acc[r][c] - mean) * inv * gv[c] + bv[c];
            if (RELU) y = fmaxf(y, 0.f);
            Y[orow + lane + 32 * c] = y;
        }
    }
}

// ---------------------------------------------------------------------------
// Fused attention kernel:  per (b,m,p):
//   vp = relu(LN(vf @ v_W + v_b))              (phase A, smem-resident)
//   h  = relu(LN([pp, vp] @ a1_W + a1_b))      (phase B, a1_W streamed)
//   attn = sigmoid(h @ a2_W + a2_b)            (warp-reduced epilogue)
// Never materializes vp/h to HBM. 32 rows/block, 96 KB dynamic smem.
// ---------------------------------------------------------------------------
__global__ void attn_kernel(const float* __restrict__ vf,
                            const float* __restrict__ vW, const float* __restrict__ vb,
                            const float* __restrict__ vg, const float* __restrict__ vbe,
                            const float* __restrict__ a1W, const float* __restrict__ a1b,
                            const float* __restrict__ ag, const float* __restrict__ abe,
                            const float* __restrict__ a2W, const float* __restrict__ a2b)
{
    extern __shared__ float sm[];
    float* vps  = sm;            // [32][256] vp tile
    float* pps  = sm + 8192;     // [32][256] pp tile (phase A: v_W tile buffer)
    float* wbuf = sm + 16384;    // [32][256] a1_W tile (phase A: X tile in first 1024)

    const int tid = threadIdx.x;
    const int wr = tid >> 5, lane = tid & 31;
    const int row0 = blockIdx.x * 32;            // rows are (b*M+m)*Np + p, p contiguous
    const int b = row0 / (MM * NPTS);
    const int p0 = row0 % NPTS;

    float acc[4][8];
    #pragma unroll
    for (int r = 0; r < 4; r++)
        #pragma unroll
        for (int c = 0; c < 8; c++) acc[r][c] = 0.f;

    // ---- Phase A: vp GEMM (K=256) ----
    for (int k0 = 0; k0 < 256; k0 += 32) {
        for (int i = tid; i < 1024; i += 256) {
            int r = i >> 5, c = i & 31;
            wbuf[i] = vf[(size_t)(row0 + r) * 256 + k0 + c];
        }
        for (int i = tid; i < 8192; i += 256) {
            int kk = i >> 8, n = i & 255;
            pps[i] = vW[(size_t)(k0 + kk) * 256 + n];
        }
        __syncthreads();
        #pragma unroll
        for (int kk = 0; kk < 32; kk++) {
            float xv[4];
            #pragma unroll
            for (int r = 0; r < 4; r++) xv[r] = wbuf[(wr * 4 + r) * 32 + kk];
            #pragma unroll
            for (int c = 0; c < 8; c++) {
                float wv = pps[kk * 256 + lane + 32 * c];
                #pragma unroll
                for (int r = 0; r < 4; r++) acc[r][c] = fmaf(xv[r], wv, acc[r][c]);
            }
        }
        __syncthreads();
    }
    // LN + relu -> vps
    {
        float gv[8], bv[8];
        #pragma unroll
        for (int c = 0; c < 8; c++) {
            int col = lane + 32 * c;
            float bb = vb[col];
            #pragma unroll
            for (int r = 0; r < 4; r++) acc[r][c] += bb;
            gv[c] = vg[col]; bv[c] = vbe[col];
        }
        #pragma unroll
        for (int r = 0; r < 4; r++) {
            float s = 0.f;
            #pragma unroll
            for (int c = 0; c < 8; c++) s += acc[r][c];
            float mean = warp_red(s) * (1.f / 256.f);
            float s2 = 0.f;
            #pragma unroll
            for (int c = 0; c < 8; c++) { float d = acc[r][c] - mean; s2 += d * d; }
            float inv = rsqrtf(warp_red(s2) * (1.f / 256.f) + 1e-5f);
            #pragma unroll
            for (int c = 0; c < 8; c++) {
                float y = (acc[r][c] - mean) * inv * gv[c] + bv[c];
                vps[(wr * 4 + r) * 256 + lane + 32 * c] = fmaxf(y, 0.f);
            }
        }
    }
    // load pp rows (overwrites phase-A weight buffer; all phase-A reads are done)
    for (int i = tid; i < 8192; i += 256) {
        int r = i >> 8, c = i & 255;
        pps[i] = g_pp[((size_t)b * NPTS + p0 + r) * 256 + c];
    }

    // ---- Phase B: h GEMM over concat [pp | vp], K=512, stream a1_W ----
    #pragma unroll
    for (int r = 0; r < 4; r++)
        #pragma unroll
        for (int c = 0; c < 8; c++) acc[r][c] = 0.f;

    for (int kt = 0; kt < 16; kt++) {
        int k0 = kt * 32;
        for (int i = tid; i < 8192; i += 256) {
            int kk = i >> 8, n = i & 255;
            wbuf[i] = a1W[(size_t)(k0 + kk) * 256 + n];
        }
        __syncthreads();
        const float* Xsrc = (k0 < 256) ? pps : vps;
        int kb = k0 & 255;
        #pragma unroll
        for (int kk = 0; kk < 32; kk++) {
            float xv[4];
            #pragma unroll
            for (int r = 0; r < 4; r++) xv[r] = Xsrc[(wr * 4 + r) * 256 + kb + kk];
            #pragma unroll
            for (int c = 0; c < 8; c++) {
                float wv = wbuf[kk * 256 + lane + 32 * c];
                #pragma unroll
                for (int r = 0; r < 4; r++) acc[r][c] = fmaf(xv[r], wv, acc[r][c]);
            }
        }
        __syncthreads();
    }

    // bias + LN + relu + dot(a2_W) + sigmoid
    {
        float gv[8], bv[8], aw[8];
        #pragma unroll
        for (int c = 0; c < 8; c++) {
            int col = lane + 32 * c;
            float bb = a1b[col];
            #pragma unroll
            for (int r = 0; r < 4; r++) acc[r][c] += bb;
            gv[c] = ag[col]; bv[c] = abe[col]; aw[c] = a2W[col];
        }
        float a2bias = a2b[0];
        #pragma unroll
        for (int r = 0; r < 4; r++) {
            float s = 0.f;
            #pragma unroll
            for (int c = 0; c < 8; c++) s += acc[r][c];
            float mean = warp_red(s) * (1.f / 256.f);
            float s2 = 0.f;
            #pragma unroll
            for (int c = 0; c < 8; c++) { float d = acc[r][c] - mean; s2 += d * d; }
            float inv = rsqrtf(warp_red(s2) * (1.f / 256.f) + 1e-5f);
            float part = 0.f;
            #pragma unroll
            for (int c = 0; c < 8; c++) {
                float y = (acc[r][c] - mean) * inv * gv[c] + bv[c];
                part = fmaf(fmaxf(y, 0.f), aw[c], part);
            }
            part = warp_red(part);
            if (lane == 0)
                g_attn[row0 + wr * 4 + r] = 1.f / (1.f + expf(-(part + a2bias)));
        }
    }
}

// ---------------------------------------------------------------------------
// Segment buffers: zero, accumulate (atomics), then refine+softmax+weighted sum
// ---------------------------------------------------------------------------
__global__ void zero_seg_kernel() {
    int i = blockIdx.x * 256 + threadIdx.x;
    if (i < NSEG) g_cnt[i] = 0.f;
    if (i < NSEG * MM) g_asum[i] = 0.f;
    if (i < NSEG * HH) g_fsum[i] = 0.f;
}

__global__ void seg_accum_kernel(const int* __restrict__ sp) {
    int q = blockIdx.x * 8 + (threadIdx.x >> 5);   // point index, one warp per point
    int lane = threadIdx.x & 31;
    int b = q / NPTS, p = q % NPTS;
    int s = sp[q];
    int seg = (s >= 0 && s < SS) ? b * SS + s : BN * SS;
    if (lane == 0) atomicAdd(&g_cnt[seg], 1.f);
    if (lane < MM) atomicAdd(&g_asum[seg * MM + lane],
                             g_attn[((size_t)b * MM + lane) * NPTS + p]);
    #pragma unroll
    for (int k = 0; k < 8; k++) {
        int c = lane + 32 * k;
        atomicAdd(&g_fsum[seg * HH + c], g_pp[(size_t)q * HH + c]);
    }
}

__global__ void refine_weighted_kernel(const int* __restrict__ sp,
                                       const float* __restrict__ vf) {
    int q = blockIdx.x * 8 + (threadIdx.x >> 5);
    int lane = threadIdx.x & 31;
    int b = q / NPTS, p = q % NPTS;
    int s = sp[q];
    bool valid = (s >= 0 && s < SS);
    int seg = valid ? b * SS + s : BN * SS;
    float rc = 1.f / fmaxf(g_cnt[seg], 1.f);

    // cosine similarity between pp row and segment-mean pp
    float dot = 0.f, nf = 0.f, nfm = 0.f;
    #pragma unroll
    for (int k = 0; k < 8; k++) {
        int c = lane + 32 * k;
        float fvv = g_pp[(size_t)q * HH + c];
        float fmv = g_fsum[seg * HH + c] * rc;
        dot = fmaf(fvv, fmv, dot);
        nf  = fmaf(fvv, fvv, nf);
        nfm = fmaf(fmv, fmv, nfm);
    }
    dot = warp_red(dot); nf = warp_red(nf); nfm = warp_red(nfm);
    float sim = dot / (fmaxf(sqrtf(nf), 1e-8f) * fmaxf(sqrtf(nfm), 1e-8f));

    // refined attention + softmax over M=8 (all lanes compute redundantly)
    float w[MM];
    float mx = -1e30f;
    #pragma unroll
    for (int m = 0; m < MM; m++) {
        float a  = g_attn[((size_t)b * MM + m) * NPTS + p];
        float am = g_asum[seg * MM + m] * rc;
        float r = valid ? (am + (a - am) * sim) : a;
        w[m] = r;
        mx = fmaxf(mx, r);
    }
    float sum = 0.f;
    #pragma unroll
    for (int m = 0; m < MM; m++) { w[m] = expf(w[m] - mx); sum += w[m]; }
    float rs = 1.f / sum;
    #pragma unroll
    for (int m = 0; m < MM; m++) w[m] *= rs;

    // weighted view-feature sum
    #pragma unroll
    for (int k = 0; k < 8; k++) {
        int c = lane + 32 * k;
        float acc = 0.f;
        #pragma unroll
        for (int m = 0; m < MM; m++)
            acc = fmaf(w[m], vf[(((size_t)b * MM + m) * NPTS + p) * 256 + c], acc);
        g_weighted[(size_t)q * HH + c] = acc;
    }
}

// ---------------------------------------------------------------------------
extern "C" void kernel_launch(void* const* d_in, const int* in_sizes, int n_in,
                              void* d_out, int out_size)
{
    const float* pf  = (const float*)d_in[0];
    const float* vf  = (const float*)d_in[1];
    const int*   sp  = (const int*)  d_in[2];
    const float* pW  = (const float*)d_in[3];
    const float* pb  = (const float*)d_in[4];
    const float* pg  = (const float*)d_in[5];
    const float* pbe = (const float*)d_in[6];
    const float* vW  = (const float*)d_in[7];
    const float* vb  = (const float*)d_in[8];
    const float* vg  = (const float*)d_in[9];
    const float* vbe = (const float*)d_in[10];
    const float* a1W = (const float*)d_in[11];
    const float* a1b = (const float*)d_in[12];
    const float* ag  = (const float*)d_in[13];
    const float* abe = (const float*)d_in[14];
    const float* a2W = (const float*)d_in[15];
    const float* a2b = (const float*)d_in[16];
    const float* fW  = (const float*)d_in[17];
    const float* fb  = (const float*)d_in[18];
    const float* fg  = (const float*)d_in[19];
    const float* fbe = (const float*)d_in[20];
    float* out = (float*)d_out;

    float *pp_ptr, *weighted_ptr, *wvp_ptr;
    cudaGetSymbolAddress((void**)&pp_ptr, g_pp);
    cudaGetSymbolAddress((void**)&weighted_ptr, g_weighted);
    cudaGetSymbolAddress((void**)&wvp_ptr, g_wvp);

    cudaFuncSetAttribute(attn_kernel, cudaFuncAttributeMaxDynamicSharedMemorySize, 96 * 1024);

    const int smem256 = (32 * 32 + 32 * 256) * 4;   // 36 KB
    const int smem512 = (32 * 16 + 16 * 512) * 4;   // 34 KB

    // 1) pp = relu(LN(pf @ p_W + p_b))
    gemm_ln_kernel<256, 32, true><<<NROWS_PP / 32, 256, smem256>>>(
        pf, nullptr, 256, 256, pW, pb, pg, pbe, pp_ptr);

    // 2) fused vp -> h -> attn
    attn_kernel<<<NROWS_V / 32, 256, 96 * 1024>>>(
        vf, vW, vb, vg, vbe, a1W, a1b, ag, abe, a2W, a2b);

    // 3) segment means
    zero_seg_kernel<<<(NSEG * HH + 255) / 256, 256>>>();
    seg_accum_kernel<<<NROWS_PP / 8, 256>>>(sp);

    // 4) refine + softmax over M + weighted view sum
    refine_weighted_kernel<<<NROWS_PP / 8, 256>>>(sp, vf);

    // 5) wvp = relu(LN(weighted @ v_W + v_b))
    gemm_ln_kernel<256, 32, true><<<NROWS_PP / 32, 256, smem256>>>(
        weighted_ptr, nullptr, 256, 256, vW, vb, vg, vbe, wvp_ptr);

    // 6) out = LN([pp, wvp] @ f_W + f_b)
    gemm_ln_kernel<512, 16, false><<<NROWS_PP / 32, 256, smem512>>>(
        pp_ptr, wvp_ptr, 256, 512, fW, fb, fg, fbe, out);
}

// round 5
// speedup vs baseline: 1.3446x; 1.3446x over previous
#include <cuda_runtime.h>
#include <cuda_bf16.h>
#include <mma.h>
#include <cstdint>
#include <math.h>

using namespace nvcuda;

// Problem constants
#define BN 4
#define MM 8
#define NPTS 4096
#define HH 256
#define FDIM 512
#define SS 128
#define NSEG (BN*SS + 1)
#define NROWS_PP (BN*NPTS)
#define NROWS_V  (BN*MM*NPTS)

// Scratch (device globals: no allocation allowed)
__device__ float g_pp[NROWS_PP * HH];
__device__ __nv_bfloat16 g_ppbf[NROWS_PP * HH];
__device__ float g_attn[NROWS_V];
__device__ float g_cnt[NSEG];
__device__ float g_asum[NSEG * MM];
__device__ float g_fsum[NSEG * HH];
__device__ float g_weighted[NROWS_PP * HH];
__device__ float g_wvp[NROWS_PP * HH];
__device__ __nv_bfloat16 g_vW16[256 * 256];   // bf16 copy of v_W [k][n]
__device__ __nv_bfloat16 g_a1W16[512 * 256];  // bf16 copy of a1_W [k][n]

__device__ __forceinline__ float warp_red(float v) {
    #pragma unroll
    for (int o = 16; o; o >>= 1) v += __shfl_xor_sync(0xffffffffu, v, o);
    return v;
}

// ===================== weight prep (bf16 copies) + zero segment buffers =====================
__global__ void prep_weights_kernel(const float* __restrict__ vW, const float* __restrict__ a1W)
{
    int i = blockIdx.x * 256 + threadIdx.x;
    if (i < 256 * 256) g_vW16[i] = __float2bfloat16(vW[i]);
    if (i < 512 * 256) g_a1W16[i] = __float2bfloat16(a1W[i]);
    if (i < NSEG) g_cnt[i] = 0.f;
    if (i < NSEG * MM) g_asum[i] = 0.f;
    if (i < NSEG * HH) g_fsum[i] = 0.f;
}

// ===================== fp32 GEMM + bias + LN (+ReLU) =====================
template<int N, int KTILE, bool RELU>
__global__ void gemm_ln_kernel(const float* __restrict__ X1, const float* __restrict__ X2,
                               int K1, int K,
                               const float* __restrict__ W, const float* __restrict__ bias,
                               const float* __restrict__ gamma, const float* __restrict__ beta,
                               float* __restrict__ Y, __nv_bfloat16* __restrict__ Ybf)
{
    constexpr int CP = N / 32;
    extern __shared__ float sm[];
    float* Xs = sm;
    float* Ws = sm + 32 * KTILE;

    const int tid = threadIdx.x;
    const int wr = tid >> 5;
    const int lane = tid & 31;
    const int row0 = blockIdx.x * 32;

    float acc[4][CP];
    #pragma unroll
    for (int r = 0; r < 4; r++) {
        #pragma unroll
        for (int c = 0; c < CP; c++) acc[r][c] = 0.f;
    }

    for (int k0 = 0; k0 < K; k0 += KTILE) {
        for (int i = tid; i < 32 * KTILE; i += 256) {
            int r = i / KTILE;
            int c = i % KTILE;
            int k = k0 + c;
            float v;
            if (k < K1) v = X1[(size_t)(row0 + r) * K1 + k];
            else        v = X2[(size_t)(row0 + r) * (K - K1) + (k - K1)];
            Xs[i] = v;
        }
        for (int i = tid; i < KTILE * N; i += 256) {
            int kk = i / N;
            int n = i % N;
            Ws[i] = W[(size_t)(k0 + kk) * N + n];
        }
        __syncthreads();
        #pragma unroll
        for (int kk = 0; kk < KTILE; kk++) {
            float xv[4];
            #pragma unroll
            for (int r = 0; r < 4; r++) xv[r] = Xs[(wr * 4 + r) * KTILE + kk];
            #pragma unroll
            for (int c = 0; c < CP; c++) {
                float wv = Ws[kk * N + lane + 32 * c];
                #pragma unroll
                for (int r = 0; r < 4; r++) acc[r][c] = fmaf(xv[r], wv, acc[r][c]);
            }
        }
        __syncthreads();
    }

    float gv[CP];
    float bv[CP];
    #pragma unroll
    for (int c = 0; c < CP; c++) {
        int col = lane + 32 * c;
        float bb = bias[col];
        #pragma unroll
        for (int r = 0; r < 4; r++) acc[r][c] += bb;
        gv[c] = gamma[col];
        bv[c] = beta[col];
    }
    #pragma unroll
    for (int r = 0; r < 4; r++) {
        float s = 0.f;
        #pragma unroll
        for (int c = 0; c < CP; c++) s += acc[r][c];
        float mean = warp_red(s) * (1.f / N);
        float s2 = 0.f;
        #pragma unroll
        for (int c = 0; c < CP; c++) {
            float d = acc[r][c] - mean;
            s2 += d * d;
        }
        float inv = rsqrtf(warp_red(s2) * (1.f / N) + 1e-5f);
        size_t orow = (size_t)(row0 + wr * 4 + r) * N;
        #pragma unroll
        for (int c = 0; c < CP; c++) {
            float y = (acc[r][c] - mean) * inv * gv[c] + bv[c];
            if (RELU) y = fmaxf(y, 0.f);
            Y[orow + lane + 32 * c] = y;
            if (Ybf) Ybf[orow + lane + 32 * c] = __float2bfloat16(y);
        }
    }
}

// ===================== WMMA bf16 fused attention kernel =====================
// Per CTA: 64 rows of (b,m,p). Phase A: vp = relu(LN(vf@vW)) kept in smem.
// Phase B: h = relu(LN([pp|vp]@a1W)); attn = sigmoid(h . a2W + a2b).
// 8 warps: warp w -> row strip (w&3)*16, N-half (w>>2)*128 (8x 16x16 frags).
// smem layout (bytes):
//   [0, 7168)          params: vb,vg,vbe,a1b,ag,abe,a2W (7 x 256 f32)
//   [7168, 72704)      Xs: 64 x 512 bf16   (cols 0..255 pp, 256..511 vf->vp)
//   [72704, 105472)    Ws: 64 x 256 bf16   (weight K-chunk)
//   [105472, 171008)   Csm: 64 x 256 f32   (accumulator staging)
#define ATTN_SMEM 171008

__global__ void __launch_bounds__(256, 1)
attn_wmma_kernel(const float* __restrict__ vf,
                 const float* __restrict__ vb, const float* __restrict__ vg,
                 const float* __restrict__ vbe,
                 const float* __restrict__ a1b, const float* __restrict__ ag,
                 const float* __restrict__ abe,
                 const float* __restrict__ a2W, const float* __restrict__ a2b)
{
    extern __shared__ char smc[];
    float* s_par = (float*)smc;
    __nv_bfloat16* Xs = (__nv_bfloat16*)(smc + 7168);
    __nv_bfloat16* Ws = (__nv_bfloat16*)(smc + 72704);
    float* Csm = (float*)(smc + 105472);

    const int tid = threadIdx.x;
    const int wid = tid >> 5;
    const int lane = tid & 31;
    const int row0 = blockIdx.x * 64;
    const int b = row0 / (MM * NPTS);
    const int p0 = row0 % NPTS;

    const int mstrip = (wid & 3) * 16;   // row offset of this warp's strip
    const int nhalf = (wid >> 2) * 128;  // col offset of this warp's N-half

    // params
    s_par[tid]        = vb[tid];
    s_par[256 + tid]  = vg[tid];
    s_par[512 + tid]  = vbe[tid];
    s_par[768 + tid]  = a1b[tid];
    s_par[1024 + tid] = ag[tid];
    s_par[1280 + tid] = abe[tid];
    s_par[1536 + tid] = a2W[tid];

    // vf -> Xs cols 256..511 (bf16)
    for (int i = tid; i < 64 * 128; i += 256) {
        int r = i >> 7;
        int pr = i & 127;
        float2 v = *(const float2*)(vf + (size_t)(row0 + r) * 256 + pr * 2);
        __nv_bfloat162 h2 = __floats2bfloat162_rn(v.x, v.y);
        *(__nv_bfloat162*)(Xs + r * 512 + 256 + pr * 2) = h2;
    }

    wmma::fragment<wmma::accumulator, 16, 16, 16, float> cf[8];
    wmma::fragment<wmma::matrix_a, 16, 16, 16, __nv_bfloat16, wmma::row_major> af;
    wmma::fragment<wmma::matrix_b, 16, 16, 16, __nv_bfloat16, wmma::row_major> bfr;

    // ================= Phase A: vf @ vW (K = 256) =================
    #pragma unroll
    for (int n = 0; n < 8; n++) wmma::fill_fragment(cf[n], 0.f);

    for (int k0 = 0; k0 < 256; k0 += 64) {
        // load weight chunk 64k x 256n
        {
            const uint2* src = (const uint2*)(g_vW16 + (size_t)k0 * 256);
            uint2* dst = (uint2*)Ws;
            for (int i = tid; i < 64 * 64; i += 256) dst[i] = src[i];
        }
        __syncthreads();
        #pragma unroll
        for (int kk = 0; kk < 64; kk += 16) {
            wmma::load_matrix_sync(af, Xs + mstrip * 512 + 256 + k0 + kk, 512);
            #pragma unroll
            for (int n = 0; n < 8; n++) {
                wmma::load_matrix_sync(bfr, Ws + kk * 256 + nhalf + n * 16, 256);
                wmma::mma_sync(cf[n], af, bfr, cf[n]);
            }
        }
        __syncthreads();
    }

    // stage accums to Csm
    #pragma unroll
    for (int n = 0; n < 8; n++)
        wmma::store_matrix_sync(Csm + mstrip * 256 + nhalf + n * 16, cf[n], 256, wmma::mem_row_major);

    // pp rows -> Xs cols 0..255
    {
        for (int i = tid; i < 64 * 32; i += 256) {
            int r = i >> 5;
            int j = i & 31;
            uint4 w = ((const uint4*)(g_ppbf + (size_t)(b * NPTS + p0 + r) * 256))[j];
            ((uint4*)(Xs + r * 512))[j] = w;
        }
    }
    __syncthreads();

    // Epilogue A: per-row LN + relu -> Xs cols 256..511 (bf16). warp w: rows w*8..w*8+7
    for (int r8 = 0; r8 < 8; r8++) {
        int row = wid * 8 + r8;
        float vv[8];
        float s1 = 0.f;
        float s2 = 0.f;
        #pragma unroll
        for (int j = 0; j < 8; j++) {
            int col = lane + 32 * j;
            float v = Csm[row * 256 + col] + s_par[col];
            vv[j] = v;
            s1 += v;
            s2 += v * v;
        }
        float mean = warp_red(s1) * (1.f / 256.f);
        float ex2 = warp_red(s2) * (1.f / 256.f);
        float inv = rsqrtf(ex2 - mean * mean + 1e-5f);
        #pragma unroll
        for (int j = 0; j < 8; j++) {
            int col = lane + 32 * j;
            float y = (vv[j] - mean) * inv * s_par[256 + col] + s_par[512 + col];
            Xs[row * 512 + 256 + col] = __float2bfloat16(fmaxf(y, 0.f));
        }
    }
    __syncthreads();

    // ================= Phase B: [pp|vp] @ a1W (K = 512) =================
    #pragma unroll
    for (int n = 0; n < 8; n++) wmma::fill_fragment(cf[n], 0.f);

    for (int k0 = 0; k0 < 512; k0 += 64) {
        {
            const uint2* src = (const uint2*)(g_a1W16 + (size_t)k0 * 256);
            uint2* dst = (uint2*)Ws;
            for (int i = tid; i < 64 * 64; i += 256) dst[i] = src[i];
        }
        __syncthreads();
        #pragma unroll
        for (int kk = 0; kk < 64; kk += 16) {
            wmma::load_matrix_sync(af, Xs + mstrip * 512 + k0 + kk, 512);
            #pragma unroll
            for (int n = 0; n < 8; n++) {
                wmma::load_matrix_sync(bfr, Ws + kk * 256 + nhalf + n * 16, 256);
                wmma::mma_sync(cf[n], af, bfr, cf[n]);
            }
        }
        __syncthreads();
    }

    #pragma unroll
    for (int n = 0; n < 8; n++)
        wmma::store_matrix_sync(Csm + mstrip * 256 + nhalf + n * 16, cf[n], 256, wmma::mem_row_major);
    __syncthreads();

    // Epilogue B: LN + relu, dot a2W, sigmoid -> g_attn
    float a2bias = a2b[0];
    for (int r8 = 0; r8 < 8; r8++) {
        int row = wid * 8 + r8;
        float vv[8];
        float s1 = 0.f;
        float s2 = 0.f;
        #pragma unroll
        for (int j = 0; j < 8; j++) {
            int col = lane + 32 * j;
            float v = Csm[row * 256 + col] + s_par[768 + col];
            vv[j] = v;
            s1 += v;
            s2 += v * v;
        }
        float mean = warp_red(s1) * (1.f / 256.f);
        float ex2 = warp_red(s2) * (1.f / 256.f);
        float inv = rsqrtf(ex2 - mean * mean + 1e-5f);
        float dotp = 0.f;
        #pragma unroll
        for (int j = 0; j < 8; j++) {
            int col = lane + 32 * j;
            float y = (vv[j] - mean) * inv * s_par[1024 + col] + s_par[1280 + col];
            dotp = fmaf(fmaxf(y, 0.f), s_par[1536 + col], dotp);
        }
        dotp = warp_red(dotp);
        if (lane == 0) {
            g_attn[row0 + row] = 1.f / (1.f + expf(-(dotp + a2bias)));
        }
    }
}

// ===================== segment mean / refine / weighted =====================
__global__ void seg_accum_kernel(const int* __restrict__ sp)
{
    int q = blockIdx.x * 8 + (threadIdx.x >> 5);
    int lane = threadIdx.x & 31;
    int b = q / NPTS;
    int p = q % NPTS;
    int s = sp[q];
    int seg = (s >= 0 && s < SS) ? (b * SS + s) : (BN * SS);
    if (lane == 0) atomicAdd(&g_cnt[seg], 1.f);
    if (lane < MM) atomicAdd(&g_asum[seg * MM + lane],
                             g_attn[((size_t)b * MM + lane) * NPTS + p]);
    #pragma unroll
    for (int k = 0; k < 8; k++) {
        int c = lane + 32 * k;
        atomicAdd(&g_fsum[seg * HH + c], g_pp[(size_t)q * HH + c]);
    }
}

__global__ void refine_weighted_kernel(const int* __restrict__ sp,
                                       const float* __restrict__ vf)
{
    int q = blockIdx.x * 8 + (threadIdx.x >> 5);
    int lane = threadIdx.x & 31;
    int b = q / NPTS;
    int p = q % NPTS;
    int s = sp[q];
    bool valid = (s >= 0 && s < SS);
    int seg = valid ? (b * SS + s) : (BN * SS);
    float rc = 1.f / fmaxf(g_cnt[seg], 1.f);

    float dot = 0.f;
    float nf = 0.f;
    float nfm = 0.f;
    #pragma unroll
    for (int k = 0; k < 8; k++) {
        int c = lane + 32 * k;
        float fvv = g_pp[(size_t)q * HH + c];
        float fmv = g_fsum[seg * HH + c] * rc;
        dot = fmaf(fvv, fmv, dot);
        nf  = fmaf(fvv, fvv, nf);
        nfm = fmaf(fmv, fmv, nfm);
    }
    dot = warp_red(dot);
    nf = warp_red(nf);
    nfm = warp_red(nfm);
    float sim = dot / (fmaxf(sqrtf(nf), 1e-8f) * fmaxf(sqrtf(nfm), 1e-8f));

    float w[MM];
    float mx = -1e30f;
    #pragma unroll
    for (int m = 0; m < MM; m++) {
        float a  = g_attn[((size_t)b * MM + m) * NPTS + p];
        float am = g_asum[seg * MM + m] * rc;
        float r = valid ? (am + (a - am) * sim) : a;
        w[m] = r;
        mx = fmaxf(mx, r);
    }
    float sum = 0.f;
    #pragma unroll
    for (int m = 0; m < MM; m++) {
        w[m] = expf(w[m] - mx);
        sum += w[m];
    }
    float rs = 1.f / sum;
    #pragma unroll
    for (int m = 0; m < MM; m++) w[m] *= rs;

    #pragma unroll
    for (int k = 0; k < 8; k++) {
        int c = lane + 32 * k;
        float acc = 0.f;
        #pragma unroll
        for (int m = 0; m < MM; m++) {
            acc = fmaf(w[m], vf[(((size_t)b * MM + m) * NPTS + p) * 256 + c], acc);
        }
        g_weighted[(size_t)q * HH + c] = acc;
    }
}

// ===================== launch =====================
extern "C" void kernel_launch(void* const* d_in, const int* in_sizes, int n_in,
                              void* d_out, int out_size)
{
    const float* pf  = (const float*)d_in[0];
    const float* vf  = (const float*)d_in[1];
    const int*   sp  = (const int*)  d_in[2];
    const float* pW  = (const float*)d_in[3];
    const float* pb  = (const float*)d_in[4];
    const float* pg  = (const float*)d_in[5];
    const float* pbe = (const float*)d_in[6];
    const float* vW  = (const float*)d_in[7];
    const float* vb  = (const float*)d_in[8];
    const float* vg  = (const float*)d_in[9];
    const float* vbe = (const float*)d_in[10];
    const float* a1W = (const float*)d_in[11];
    const float* a1b = (const float*)d_in[12];
    const float* ag  = (const float*)d_in[13];
    const float* abe = (const float*)d_in[14];
    const float* a2W = (const float*)d_in[15];
    const float* a2b = (const float*)d_in[16];
    const float* fW  = (const float*)d_in[17];
    const float* fb  = (const float*)d_in[18];
    const float* fg  = (const float*)d_in[19];
    const float* fbe = (const float*)d_in[20];
    float* out = (float*)d_out;

    float* pp_ptr = 0;
    float* weighted_ptr = 0;
    float* wvp_ptr = 0;
    __nv_bfloat16* ppbf_ptr = 0;
    cudaGetSymbolAddress((void**)&pp_ptr, g_pp);
    cudaGetSymbolAddress((void**)&weighted_ptr, g_weighted);
    cudaGetSymbolAddress((void**)&wvp_ptr, g_wvp);
    cudaGetSymbolAddress((void**)&ppbf_ptr, g_ppbf);

    cudaFuncSetAttribute(attn_wmma_kernel, cudaFuncAttributeMaxDynamicSharedMemorySize, ATTN_SMEM);

    const int smem256 = (32 * 32 + 32 * 256) * 4;
    const int smem512 = (32 * 16 + 16 * 512) * 4;

    // 0) bf16 weight copies + zero segment buffers
    prep_weights_kernel<<<512, 256>>>(vW, a1W);

    // 1) pp = relu(LN(pf @ p_W + p_b))  (+ bf16 copy)
    gemm_ln_kernel<256, 32, true><<<NROWS_PP / 32, 256, smem256>>>(
        pf, (const float*)0, 256, 256, pW, pb, pg, pbe, pp_ptr, ppbf_ptr);

    // 2) fused vp -> h -> attn on HMMA tensor cores
    attn_wmma_kernel<<<NROWS_V / 64, 256, ATTN_SMEM>>>(
        vf, vb, vg, vbe, a1b, ag, abe, a2W, a2b);

    // 3) segment means
    seg_accum_kernel<<<NROWS_PP / 8, 256>>>(sp);

    // 4) refine + softmax over M + weighted view sum
    refine_weighted_kernel<<<NROWS_PP / 8, 256>>>(sp, vf);

    // 5) wvp = relu(LN(weighted @ v_W + v_b))
    gemm_ln_kernel<256, 32, true><<<NROWS_PP / 32, 256, smem256>>>(
        weighted_ptr, (const float*)0, 256, 256, vW, vb, vg, vbe, wvp_ptr, (__nv_bfloat16*)0);

    // 6) out = LN([pp, wvp] @ f_W + f_b)
    gemm_ln_kernel<512, 16, false><<<NROWS_PP / 32, 256, smem512>>>(
        pp_ptr, wvp_ptr, 256, 512, fW, fb, fg, fbe, out, (__nv_bfloat16*)0);
}